// round 2
// baseline (speedup 1.0000x reference)
#include <cuda_runtime.h>

#define ENT   250000
#define BSZ   32768
#define KNEG  8
#define NFLAT (BSZ * KNEG)      // 262144
#define NBP   (BSZ / 256)       // 128 blocks for pos ranking
#define NBN   (NFLAT / 256)     // 1024 blocks for neg ranking
#define DIM   128

// ---------------- scratch (device globals; no allocation allowed) ----------
__device__ float g_inv_in[64];
__device__ float g_inv_out[64];
__device__ int   g_cnt_p[4 * NBP];
__device__ int   g_cnt_n[4 * NBN];
__device__ int   g_off_p[4 * NBP];
__device__ int   g_off_n[4 * NBN];
__device__ int   g_base_p[4];
__device__ int   g_base_n[4];
__device__ int   g_spos[BSZ];
__device__ int   g_sneg[NFLAT];
__device__ float g_logpos[BSZ];
__device__ float g_logneg[NFLAT];

// ---------------- helpers --------------------------------------------------
__device__ __forceinline__ float warp_sum(float v) {
    v += __shfl_xor_sync(0xffffffffu, v, 16);
    v += __shfl_xor_sync(0xffffffffu, v, 8);
    v += __shfl_xor_sync(0xffffffffu, v, 4);
    v += __shfl_xor_sync(0xffffffffu, v, 2);
    v += __shfl_xor_sync(0xffffffffu, v, 1);
    return v;
}

__device__ __forceinline__ float dot4(float4 a, float4 b) {
    return a.x * b.x + a.y * b.y + a.z * b.z + a.w * b.w;
}

// log(sigmoid(x)), numerically stable
__device__ __forceinline__ float logsigf(float x) {
    float ax = fabsf(x);
    return fminf(x, 0.0f) - log1pf(__expf(-ax));
}

// ---------------- 0. inverse squared (clamped) norms of the map tables -----
__global__ void inv_kernel(const float* __restrict__ in_map,
                           const float* __restrict__ out_map) {
    int w = (blockIdx.x * blockDim.x + threadIdx.x) >> 5;
    int lane = threadIdx.x & 31;
    if (w >= 128) return;
    const float* src = (w < 64) ? in_map + (size_t)w * DIM
                                : out_map + (size_t)(w - 64) * DIM;
    float4 m = *reinterpret_cast<const float4*>(src + lane * 4);
    float p = warp_sum(dot4(m, m));
    float c = fmaxf(sqrtf(p), 1e-12f);
    float inv = 1.0f / (c * c);
    if (lane == 0) {
        if (w < 64) g_inv_in[w] = inv;
        else        g_inv_out[w - 64] = inv;
    }
}

// ---------------- 1. per-block branch histograms ---------------------------
__global__ __launch_bounds__(256) void hist_kernel(const int* __restrict__ ilab,
                                                   const int* __restrict__ tlab,
                                                   int mode /*0=pos,1=neg*/) {
    __shared__ int c[4];
    if (threadIdx.x < 4) c[threadIdx.x] = 0;
    __syncthreads();
    int idx = blockIdx.x * 256 + threadIdx.x;
    int il = mode ? ilab[idx >> 3] : ilab[idx];
    int tl = tlab[idx];
    int v = ((il >= ENT) ? 2 : 0) + ((tl >= ENT) ? 1 : 0);
    atomicAdd(&c[v], 1);
    __syncthreads();
    if (threadIdx.x < 4) {
        if (mode) g_cnt_n[threadIdx.x * NBN + blockIdx.x] = c[threadIdx.x];
        else      g_cnt_p[threadIdx.x * NBP + blockIdx.x] = c[threadIdx.x];
    }
}

// ---------------- 2. single-block scans (Hillis-Steele, width 1024) --------
__global__ __launch_bounds__(1024) void scan_kernel() {
    __shared__ int sm[1024];
    __shared__ int tot[4];
    int t = threadIdx.x;

    // pos
    for (int v = 0; v < 4; v++) {
        int x = (t < NBP) ? g_cnt_p[v * NBP + t] : 0;
        sm[t] = x;
        __syncthreads();
        for (int d = 1; d < 1024; d <<= 1) {
            int y = (t >= d) ? sm[t - d] : 0;
            __syncthreads();
            sm[t] += y;
            __syncthreads();
        }
        if (t < NBP) g_off_p[v * NBP + t] = sm[t] - x;
        if (t == 1023) tot[v] = sm[1023];
        __syncthreads();
    }
    if (t == 0) {
        int acc = 0;
        for (int v = 0; v < 4; v++) { g_base_p[v] = acc; acc += tot[v]; }
    }
    __syncthreads();

    // neg
    for (int v = 0; v < 4; v++) {
        int x = (t < NBN) ? g_cnt_n[v * NBN + t] : 0;
        sm[t] = x;
        __syncthreads();
        for (int d = 1; d < 1024; d <<= 1) {
            int y = (t >= d) ? sm[t - d] : 0;
            __syncthreads();
            sm[t] += y;
            __syncthreads();
        }
        if (t < NBN) g_off_n[v * NBN + t] = sm[t] - x;
        if (t == 1023) tot[v] = sm[1023];
        __syncthreads();
    }
    if (t == 0) {
        int acc = 0;
        for (int v = 0; v < 4; v++) { g_base_n[v] = acc; acc += tot[v]; }
    }
}

// ---------------- 3. stable counting-sort positions ------------------------
__global__ __launch_bounds__(256) void rank_kernel(const int* __restrict__ ilab,
                                                   const int* __restrict__ tlab,
                                                   int mode) {
    int idx = blockIdx.x * 256 + threadIdx.x;
    int il = mode ? ilab[idx >> 3] : ilab[idx];
    int tl = tlab[idx];
    int v = ((il >= ENT) ? 2 : 0) + ((tl >= ENT) ? 1 : 0);

    unsigned b0 = __ballot_sync(0xffffffffu, v == 0);
    unsigned b1 = __ballot_sync(0xffffffffu, v == 1);
    unsigned b2 = __ballot_sync(0xffffffffu, v == 2);
    unsigned b3 = __ballot_sync(0xffffffffu, v == 3);
    unsigned mybal = (v == 0) ? b0 : (v == 1) ? b1 : (v == 2) ? b2 : b3;

    int lane = threadIdx.x & 31, w = threadIdx.x >> 5;
    int inw = __popc(mybal & ((1u << lane) - 1u));

    __shared__ int wc[8][4];
    if (lane == 0) {
        wc[w][0] = __popc(b0); wc[w][1] = __popc(b1);
        wc[w][2] = __popc(b2); wc[w][3] = __popc(b3);
    }
    __syncthreads();
    int wb = 0;
    for (int ww = 0; ww < w; ww++) wb += wc[ww][v];
    int local = wb + inw;

    if (mode) g_sneg[idx] = g_base_n[v] + g_off_n[v * NBN + blockIdx.x] + local;
    else      g_spos[idx] = g_base_p[v] + g_off_p[v * NBP + blockIdx.x] + local;
}

// ---------------- 4. main gather + dot kernel (warp per input row) ---------
__global__ __launch_bounds__(256) void main_kernel(
    const float* __restrict__ in_ent, const float* __restrict__ out_ent,
    const float* __restrict__ in_rel, const float* __restrict__ out_rel,
    const float* __restrict__ in_map, const float* __restrict__ out_map,
    const int* __restrict__ ilab, const int* __restrict__ plab,
    const int* __restrict__ nlab) {
    int gw = (blockIdx.x * 256 + threadIdx.x) >> 5;
    int lane = threadIdx.x & 31;
    if (gw >= BSZ) return;
    int i = gw;

    int il = __ldg(&ilab[i]);
    bool mi = il < ENT;
    int iid = mi ? il : il - ENT;
    int iidr = min(iid, 63);

    const float* inb = mi ? in_ent + (size_t)iid * DIM
                          : in_rel + (size_t)iidr * DIM;
    float4 vin = *reinterpret_cast<const float4*>(inb + lane * 4);

    float4 vom = make_float4(0.f, 0.f, 0.f, 0.f);
    float inv_o = 0.f;
    if (!mi) {  // warp-uniform, rare
        vom = *reinterpret_cast<const float4*>(out_map + (size_t)iidr * DIM + lane * 4);
        inv_o = g_inv_out[iidr];
    }

    // 9 target labels: [0] = pos, [1..8] = negs
    int tl[9];
    tl[0] = __ldg(&plab[i]);
#pragma unroll
    for (int k = 0; k < 8; k++) tl[k + 1] = __ldg(&nlab[i * 8 + k]);

    // compute per-target branch info as a bitmask (avoids bool arrays ->
    // local memory) and issue all 9 float4 gathers back-to-back for MLP=9
    unsigned entmask = 0;
    int pidr_[9];
    const float* op_[9];
#pragma unroll
    for (int k = 0; k < 9; k++) {
        int t = tl[k];
        bool mp = t < ENT;
        entmask |= (mp ? 1u : 0u) << k;
        int pid = mp ? t : t - ENT;
        int pidr = min(pid, 63);
        pidr_[k] = pidr;
        op_[k] = (mp ? out_ent + (size_t)pid * DIM
                     : out_rel + (size_t)pidr * DIM) + lane * 4;
    }
    float4 ov[9];
#pragma unroll
    for (int k = 0; k < 9; k++)
        ov[k] = *reinterpret_cast<const float4*>(op_[k]);

    // fetch scatter destinations early (independent loads)
    int spos = __ldg(&g_spos[i]);
    int sneg[8];
#pragma unroll
    for (int k = 0; k < 8; k++) sneg[k] = __ldg(&g_sneg[i * 8 + k]);

#pragma unroll
    for (int k = 0; k < 9; k++) {
        bool mp = (entmask >> k) & 1u;
        int pidr = pidr_[k];
        float4 a = vin;
        float4 o = ov[k];
        if (mi && !mp) {  // project input embedding (rare, warp-uniform)
            float4 m = *reinterpret_cast<const float4*>(in_map + (size_t)pidr * DIM + lane * 4);
            float s = warp_sum(dot4(vin, m)) * g_inv_in[pidr];
            a.x = vin.x - s * m.x; a.y = vin.y - s * m.y;
            a.z = vin.z - s * m.z; a.w = vin.w - s * m.w;
        }
        if (!mi && mp) {  // project output embedding (rare, warp-uniform)
            float s2 = warp_sum(dot4(o, vom)) * inv_o;
            o.x -= s2 * vom.x; o.y -= s2 * vom.y;
            o.z -= s2 * vom.z; o.w -= s2 * vom.w;
        }
        float d = warp_sum(dot4(a, o));
        if (k > 0) d = -d;
        float lg = logsigf(d);
        if (lane == 0) {
            if (k == 0) g_logpos[spos] = lg;
            else        g_logneg[sneg[k - 1]] = lg;
        }
    }
}

// ---------------- 5. finalize ----------------------------------------------
__global__ __launch_bounds__(256) void final_kernel(float* __restrict__ out) {
    int j = blockIdx.x * 256 + threadIdx.x;
    if (j < BSZ) {
        float s = g_logpos[j];
        const float4* p = reinterpret_cast<const float4*>(g_logneg + (size_t)j * 8);
        float4 a = p[0], b = p[1];
        s += a.x + a.y + a.z + a.w + b.x + b.y + b.z + b.w;
        out[j] = -s;
    }
}

// ---------------- launch ----------------------------------------------------
extern "C" void kernel_launch(void* const* d_in, const int* in_sizes, int n_in,
                              void* d_out, int out_size) {
    const float* in_ent  = (const float*)d_in[0];
    const float* out_ent = (const float*)d_in[1];
    const float* in_rel  = (const float*)d_in[2];
    const float* out_rel = (const float*)d_in[3];
    const float* in_map  = (const float*)d_in[4];
    const float* out_map = (const float*)d_in[5];
    const int*   ilab    = (const int*)d_in[6];
    const int*   plab    = (const int*)d_in[7];
    const int*   nlab    = (const int*)d_in[8];
    float* out = (float*)d_out;

    inv_kernel<<<16, 256>>>(in_map, out_map);
    hist_kernel<<<NBP, 256>>>(ilab, plab, 0);
    hist_kernel<<<NBN, 256>>>(ilab, nlab, 1);
    scan_kernel<<<1, 1024>>>();
    rank_kernel<<<NBP, 256>>>(ilab, plab, 0);
    rank_kernel<<<NBN, 256>>>(ilab, nlab, 1);
    main_kernel<<<BSZ / 8, 256>>>(in_ent, out_ent, in_rel, out_rel,
                                  in_map, out_map, ilab, plab, nlab);
    final_kernel<<<BSZ / 256, 256>>>(out);
}

// round 3
// speedup vs baseline: 1.0275x; 1.0275x over previous
#include <cuda_runtime.h>

#define ENT   250000
#define BSZ   32768
#define KNEG  8
#define NFLAT (BSZ * KNEG)      // 262144
#define DIM   128
#define CAP   1024              // max rare (branch!=0) entries per list; actual ~20/~90

// ---------------- scratch (device globals; no allocation allowed) ----------
__device__ float g_inv_in[64];
__device__ float g_inv_out[64];
__device__ int   g_np;                 // rare count, pos list
__device__ int   g_nn;                 // rare count, neg list
__device__ int   g_raw_p[CAP];         // packed (idx<<2)|v, unsorted
__device__ int   g_raw_n[CAP];
__device__ int   g_sp_idx[CAP];        // sorted rare indices (pos)
__device__ int   g_sp_pos[CAP];        // their permuted destinations
__device__ int   g_sn_idx[CAP];
__device__ int   g_sn_pos[CAP];
__device__ float g_logpos[BSZ];
__device__ float g_logneg[NFLAT];

// ---------------- helpers --------------------------------------------------
__device__ __forceinline__ float warp_sum(float v) {
    v += __shfl_xor_sync(0xffffffffu, v, 16);
    v += __shfl_xor_sync(0xffffffffu, v, 8);
    v += __shfl_xor_sync(0xffffffffu, v, 4);
    v += __shfl_xor_sync(0xffffffffu, v, 2);
    v += __shfl_xor_sync(0xffffffffu, v, 1);
    return v;
}

__device__ __forceinline__ float dot4(float4 a, float4 b) {
    return a.x * b.x + a.y * b.y + a.z * b.z + a.w * b.w;
}

__device__ __forceinline__ float logsigf(float x) {
    float ax = fabsf(x);
    return fminf(x, 0.0f) - log1pf(__expf(-ax));
}

// count of arr[t] < key over sorted arr[0..n)
__device__ __forceinline__ int lbound(const int* arr, int n, int key) {
    int lo = 0, hi = n;
    while (lo < hi) {
        int mid = (lo + hi) >> 1;
        if (arr[mid] < key) lo = mid + 1; else hi = mid;
    }
    return lo;
}

// ---------------- 0. init: inv norms + zero the rare counters ---------------
__global__ void init_kernel(const float* __restrict__ in_map,
                            const float* __restrict__ out_map) {
    if (blockIdx.x == 0 && threadIdx.x == 0) { g_np = 0; g_nn = 0; }
    int w = (blockIdx.x * blockDim.x + threadIdx.x) >> 5;
    int lane = threadIdx.x & 31;
    if (w >= 128) return;
    const float* src = (w < 64) ? in_map + (size_t)w * DIM
                                : out_map + (size_t)(w - 64) * DIM;
    float4 m = *reinterpret_cast<const float4*>(src + lane * 4);
    float p = warp_sum(dot4(m, m));
    float c = fmaxf(sqrtf(p), 1e-12f);
    float inv = 1.0f / (c * c);
    if (lane == 0) {
        if (w < 64) g_inv_in[w] = inv;
        else        g_inv_out[w - 64] = inv;
    }
}

// ---------------- 1. detect rare (branch != 0) pairs ------------------------
// grid covers BSZ (pos) followed by NFLAT (neg)
__global__ __launch_bounds__(256) void detect_kernel(const int* __restrict__ ilab,
                                                     const int* __restrict__ plab,
                                                     const int* __restrict__ nlab) {
    int g = blockIdx.x * 256 + threadIdx.x;
    if (g < BSZ) {
        int il = ilab[g], tl = plab[g];
        int v = ((il >= ENT) ? 2 : 0) + ((tl >= ENT) ? 1 : 0);
        if (v != 0) {
            int slot = atomicAdd(&g_np, 1);
            if (slot < CAP) g_raw_p[slot] = (g << 2) | v;
        }
    } else {
        int idx = g - BSZ;
        if (idx < NFLAT) {
            int il = ilab[idx >> 3], tl = nlab[idx];
            int v = ((il >= ENT) ? 2 : 0) + ((tl >= ENT) ? 1 : 0);
            if (v != 0) {
                int slot = atomicAdd(&g_nn, 1);
                if (slot < CAP) g_raw_n[slot] = (idx << 2) | v;
            }
        }
    }
}

// ---------------- 2. organize: sort tiny lists, compute destinations --------
// Stable counting-sort semantics: branch-0 block first, then branch 1,2,3,
// each in original-index order. For a rare entry (branch v) at sorted-list
// rank t: dest = base[v] + (#same-branch entries before it).
__global__ __launch_bounds__(1024) void organize_kernel() {
    __shared__ int s_pk[CAP];
    __shared__ int cnt[4];
    int t = threadIdx.x;

    // ---- pos list ----
    int np = min(g_np, CAP);
    if (t < np) s_pk[t] = g_raw_p[t];
    __syncthreads();
    if (t < np) {
        int my = s_pk[t];
        int rank = 0;                       // indices unique -> strict order
        for (int j = 0; j < np; j++) rank += (s_pk[j] < my) ? 1 : 0;
        // write sorted into globals via rank
        g_sp_idx[rank] = my >> 2;
        g_sp_pos[rank] = my;                // temp: keep packed for phase 2
    }
    __syncthreads();
    if (t == 0) {
        int c1 = 0, c2 = 0, c3 = 0;
        for (int j = 0; j < np; j++) {
            int v = g_sp_pos[j] & 3;
            c1 += (v == 1); c2 += (v == 2); c3 += (v == 3);
        }
        cnt[0] = BSZ - np;                  // branch-0 count
        cnt[1] = c1; cnt[2] = c2; cnt[3] = c3;
    }
    __syncthreads();
    if (t < np) {
        int v = g_sp_pos[t] & 3;
        int same = 0;
        for (int j = 0; j < t; j++) same += ((g_sp_pos[j] & 3) == v) ? 1 : 0;
        int base = cnt[0];
        if (v >= 2) base += cnt[1];
        if (v == 3) base += cnt[2];
        g_sp_pos[t] = base + same;          // overwrite with final dest
    }
    __syncthreads();

    // ---- neg list ----
    int nn = min(g_nn, CAP);
    if (t < nn) s_pk[t] = g_raw_n[t];
    __syncthreads();
    if (t < nn) {
        int my = s_pk[t];
        int rank = 0;
        for (int j = 0; j < nn; j++) rank += (s_pk[j] < my) ? 1 : 0;
        g_sn_idx[rank] = my >> 2;
        g_sn_pos[rank] = my;
    }
    __syncthreads();
    if (t == 0) {
        int c1 = 0, c2 = 0, c3 = 0;
        for (int j = 0; j < nn; j++) {
            int v = g_sn_pos[j] & 3;
            c1 += (v == 1); c2 += (v == 2); c3 += (v == 3);
        }
        cnt[0] = NFLAT - nn;
        cnt[1] = c1; cnt[2] = c2; cnt[3] = c3;
    }
    __syncthreads();
    if (t < nn) {
        int v = g_sn_pos[t] & 3;
        int same = 0;
        for (int j = 0; j < t; j++) same += ((g_sn_pos[j] & 3) == v) ? 1 : 0;
        int base = cnt[0];
        if (v >= 2) base += cnt[1];
        if (v == 3) base += cnt[2];
        g_sn_pos[t] = base + same;
    }
}

// ---------------- 3. main gather + dot kernel (warp per input row) ----------
__global__ __launch_bounds__(256) void main_kernel(
    const float* __restrict__ in_ent, const float* __restrict__ out_ent,
    const float* __restrict__ in_rel, const float* __restrict__ out_rel,
    const float* __restrict__ in_map, const float* __restrict__ out_map,
    const int* __restrict__ ilab, const int* __restrict__ plab,
    const int* __restrict__ nlab) {
    __shared__ int sp_idx[CAP], sp_pos[CAP], sn_idx[CAP], sn_pos[CAP];
    __shared__ int s_np, s_nn;

    if (threadIdx.x == 0) { s_np = min(g_np, CAP); s_nn = min(g_nn, CAP); }
    __syncthreads();
    int np = s_np, nn = s_nn;
    for (int t = threadIdx.x; t < np; t += 256) {
        sp_idx[t] = g_sp_idx[t]; sp_pos[t] = g_sp_pos[t];
    }
    for (int t = threadIdx.x; t < nn; t += 256) {
        sn_idx[t] = g_sn_idx[t]; sn_pos[t] = g_sn_pos[t];
    }
    __syncthreads();

    int i = (blockIdx.x * 256 + threadIdx.x) >> 5;   // grid sized exactly BSZ warps
    int lane = threadIdx.x & 31;

    int il = __ldg(&ilab[i]);
    bool mi = il < ENT;
    int iid = mi ? il : il - ENT;
    int iidr = min(iid, 63);

    const float* inb = mi ? in_ent + (size_t)iid * DIM
                          : in_rel + (size_t)iidr * DIM;
    float4 vin = *reinterpret_cast<const float4*>(inb + lane * 4);

    float4 vom = make_float4(0.f, 0.f, 0.f, 0.f);
    float inv_o = 0.f;
    if (!mi) {                      // warp-uniform, rare
        vom = *reinterpret_cast<const float4*>(out_map + (size_t)iidr * DIM + lane * 4);
        inv_o = g_inv_out[iidr];
    }

    // 9 target labels: [0] = pos, [1..8] = negs
    int tl[9];
    tl[0] = __ldg(&plab[i]);
#pragma unroll
    for (int k = 0; k < 8; k++) tl[k + 1] = __ldg(&nlab[i * 8 + k]);

    unsigned entmask = 0;
    int pidr_[9];
    const float* op_[9];
#pragma unroll
    for (int k = 0; k < 9; k++) {
        int t = tl[k];
        bool mp = t < ENT;
        entmask |= (mp ? 1u : 0u) << k;
        int pid = mp ? t : t - ENT;
        int pidr = min(pid, 63);
        pidr_[k] = pidr;
        op_[k] = (mp ? out_ent + (size_t)pid * DIM
                     : out_rel + (size_t)pidr * DIM) + lane * 4;
    }
    float4 ov[9];
#pragma unroll
    for (int k = 0; k < 9; k++)
        ov[k] = *reinterpret_cast<const float4*>(op_[k]);

    float mylg = 0.f;               // lane k (k<9) keeps pair k's logsigmoid
#pragma unroll
    for (int k = 0; k < 9; k++) {
        bool mp = (entmask >> k) & 1u;
        int pidr = pidr_[k];
        float4 a = vin;
        float4 o = ov[k];
        if (mi && !mp) {            // project input embedding (rare, warp-uniform)
            float4 m = *reinterpret_cast<const float4*>(in_map + (size_t)pidr * DIM + lane * 4);
            float s = warp_sum(dot4(vin, m)) * g_inv_in[pidr];
            a.x = vin.x - s * m.x; a.y = vin.y - s * m.y;
            a.z = vin.z - s * m.z; a.w = vin.w - s * m.w;
        }
        if (!mi && mp) {            // project output embedding (rare, warp-uniform)
            float s2 = warp_sum(dot4(o, vom)) * inv_o;
            o.x -= s2 * vom.x; o.y -= s2 * vom.y;
            o.z -= s2 * vom.z; o.w -= s2 * vom.w;
        }
        float d = warp_sum(dot4(a, o));
        if (k > 0) d = -d;
        float lg = logsigf(d);      // uniform across warp
        if (lane == k) mylg = lg;
    }

    // lanes 0..8 compute destinations in parallel and scatter
    if (lane < 9) {
        bool mp = (entmask >> lane) & 1u;
        int v = (mi ? 0 : 2) + (mp ? 0 : 1);
        if (lane == 0) {
            int dest;
            if (v == 0) dest = i - lbound(sp_idx, np, i);
            else {
                int t = lbound(sp_idx, np, i);   // exact match exists
                dest = sp_pos[t];
            }
            g_logpos[dest] = mylg;
        } else {
            int idx = i * 8 + (lane - 1);
            int dest;
            if (v == 0) dest = idx - lbound(sn_idx, nn, idx);
            else {
                int t = lbound(sn_idx, nn, idx);
                dest = sn_pos[t];
            }
            g_logneg[dest] = mylg;
        }
    }
}

// ---------------- 4. finalize -----------------------------------------------
__global__ __launch_bounds__(256) void final_kernel(float* __restrict__ out) {
    int j = blockIdx.x * 256 + threadIdx.x;
    if (j < BSZ) {
        float s = g_logpos[j];
        const float4* p = reinterpret_cast<const float4*>(g_logneg + (size_t)j * 8);
        float4 a = p[0], b = p[1];
        s += a.x + a.y + a.z + a.w + b.x + b.y + b.z + b.w;
        out[j] = -s;
    }
}

// ---------------- launch ----------------------------------------------------
extern "C" void kernel_launch(void* const* d_in, const int* in_sizes, int n_in,
                              void* d_out, int out_size) {
    const float* in_ent  = (const float*)d_in[0];
    const float* out_ent = (const float*)d_in[1];
    const float* in_rel  = (const float*)d_in[2];
    const float* out_rel = (const float*)d_in[3];
    const float* in_map  = (const float*)d_in[4];
    const float* out_map = (const float*)d_in[5];
    const int*   ilab    = (const int*)d_in[6];
    const int*   plab    = (const int*)d_in[7];
    const int*   nlab    = (const int*)d_in[8];
    float* out = (float*)d_out;

    init_kernel<<<16, 256>>>(in_map, out_map);
    detect_kernel<<<(BSZ + NFLAT + 255) / 256, 256>>>(ilab, plab, nlab);
    organize_kernel<<<1, 1024>>>();
    main_kernel<<<BSZ / 8, 256>>>(in_ent, out_ent, in_rel, out_rel,
                                  in_map, out_map, ilab, plab, nlab);
    final_kernel<<<BSZ / 256, 256>>>(out);
}